// round 16
// baseline (speedup 1.0000x reference)
#include <cuda_runtime.h>
#include <cuda_fp16.h>
#include <cstdint>

// ---------------------------------------------------------------------------
// Fused single-head attention, fp32 in/out. fp16 mma.sync (m16n8k16) GEMMs.
// CTA tile 128x256, BK=64, NST=4 (192KB smem), 16 compute + 4 producer warps.
// Early empty-arrive; merged softmax+V-transpose aux kernel.
//   B=8, S=2048, D=1024
// ---------------------------------------------------------------------------

#define BATCH 8
#define SEQ   2048
#define DIM   1024
#define MTOT  (BATCH * SEQ)      // 16384
#define N3    (3 * DIM)          // 3072

#define BM 128
#define BN 256
#define BK 64
#define NST 4
#define A_BYTES 16384            // 128 rows * 128 B
#define STAGE_BYTES 49152        // A 16384 + B 32768
#define SMEM_DYN (NST * STAGE_BYTES)
#define NTHREADS 640             // 16 compute warps + 4 producer warps

// scratch (device globals — no cudaMalloc allowed)
__device__ __half g_xh[(size_t)MTOT * DIM];
__device__ __half g_Wt[3 * (size_t)DIM * DIM];
__device__ __half g_QKV[(size_t)MTOT * N3];
__device__ float  g_S[(size_t)BATCH * SEQ * SEQ];
__device__ __half g_A[(size_t)BATCH * SEQ * SEQ];
__device__ __half g_Vt[(size_t)BATCH * DIM * SEQ];
__device__ float  g_b3[N3];

__device__ __forceinline__ uint32_t smem_u32(const void* p) {
    uint32_t a;
    asm("{ .reg .u64 t; cvta.to.shared.u64 t, %1; cvt.u32.u64 %0, t; }" : "=r"(a) : "l"(p));
    return a;
}

__device__ __forceinline__ void cp_async16(uint32_t dst, const void* src) {
    asm volatile("cp.async.cg.shared.global [%0], [%1], 16;" :: "r"(dst), "l"(src) : "memory");
}
__device__ __forceinline__ void cp_async_arrive(uint32_t mbar) {
    asm volatile("cp.async.mbarrier.arrive.noinc.shared::cta.b64 [%0];" :: "r"(mbar) : "memory");
}

#define MB_INIT(addr, cnt) \
    asm volatile("mbarrier.init.shared.b64 [%0], %1;" :: "r"(addr), "r"((uint32_t)(cnt)) : "memory")
#define MB_ARRIVE(addr) \
    asm volatile("mbarrier.arrive.release.cta.shared::cta.b64 _, [%0];" :: "r"(addr) : "memory")
#define MB_WAIT_PARITY(addr, parity) do {                                              \
    uint32_t _m = (addr); uint32_t _p = (parity); uint32_t _d;                         \
    asm volatile("{ .reg .pred p; mbarrier.try_wait.parity.acquire.cta.shared::cta.b64 p, [%1], %2; selp.b32 %0, 1, 0, p; }" \
                 : "=r"(_d) : "r"(_m), "r"(_p) : "memory");                            \
    while (!_d) {                                                                      \
        asm volatile("{ .reg .pred p; mbarrier.try_wait.parity.acquire.cta.shared::cta.b64 p, [%1], %2, 0x989680; selp.b32 %0, 1, 0, p; }" \
                     : "=r"(_d) : "r"(_m), "r"(_p) : "memory");                        \
    }                                                                                  \
} while (0)

__device__ __forceinline__ void ldsm4(uint32_t* r, uint32_t addr) {
    asm volatile("ldmatrix.sync.aligned.m8n8.x4.shared.b16 {%0,%1,%2,%3}, [%4];"
        : "=r"(r[0]), "=r"(r[1]), "=r"(r[2]), "=r"(r[3]) : "r"(addr));
}

__device__ __forceinline__ void mma16(float* c, const uint32_t* a, uint32_t b0, uint32_t b1) {
    asm volatile(
        "mma.sync.aligned.m16n8k16.row.col.f32.f16.f16.f32 "
        "{%0,%1,%2,%3}, {%4,%5,%6,%7}, {%8,%9}, {%0,%1,%2,%3};"
        : "+f"(c[0]), "+f"(c[1]), "+f"(c[2]), "+f"(c[3])
        : "r"(a[0]), "r"(a[1]), "r"(a[2]), "r"(a[3]), "r"(b0), "r"(b1));
}

// smem tile rows of 128B (64 halves); 16B-chunk swizzle c ^= (row & 7)
__device__ __forceinline__ uint32_t sw_off(int row, int kc) {
    return (uint32_t)(row * 128 + ((kc ^ (row & 7)) << 4));
}
__device__ __forceinline__ uint32_t ldsm_addr(uint32_t base, int rowbase, int ks, int lane) {
    const int row = rowbase + (lane & 7) + (lane & 8);
    const int kc = 2 * ks + ((lane >> 4) & 1);
    return base + sw_off(row, kc);
}

// ------------------------------ GEMM ---------------------------------------
// C[M,N] = alpha * A[M,K] @ B[N,K]^T (+bias). A,B fp16 K-major.
// out_half: 1 -> C half, 0 -> C float. K = nk*64. M%128==0, N%256==0.
__global__ void __launch_bounds__(NTHREADS, 1)
gemm_nt_h(const __half* __restrict__ A, const __half* __restrict__ B,
          const float* __restrict__ bias, void* __restrict__ Cv,
          int lda, int ldb, int ldc, float alpha, int out_half, int nk,
          long long sA, long long sB, long long sC)
{
    extern __shared__ char smem[];
    __shared__ __align__(8) unsigned long long mbar[2 * NST];

    A += (long long)blockIdx.z * sA;
    B += (long long)blockIdx.z * sB;

    const int bm = blockIdx.y * BM;
    const int bn = blockIdx.x * BN;
    const int tid  = threadIdx.x;
    const int lane = tid & 31;
    const int wid  = tid >> 5;

    const uint32_t sb0 = smem_u32(smem);
    const uint32_t mb  = smem_u32(&mbar[0]);   // full[s]=mb+8s, empty[s]=mb+32+8s

    if (tid == 0) {
#pragma unroll
        for (int s = 0; s < NST; ++s) {
            MB_INIT(mb + 8 * s, 128);       // full: 128 producer threads
            MB_INIT(mb + 32 + 8 * s, 512);  // empty: 512 compute threads
        }
    }
    __syncthreads();

    if (wid >= 16) {
        // ------------------------- producer warps (4) ----------------------
        const int pt = tid - 512;   // 0..127
        for (int i = 0; i < nk; ++i) {
            const int s = i & (NST - 1);
            const int u = i >> 2;
            if (i >= NST) MB_WAIT_PARITY(mb + 32 + 8 * s, (uint32_t)((u - 1) & 1));
            const uint32_t st = sb0 + (uint32_t)s * STAGE_BYTES;
            const int k0 = i * BK;
            // A: 1024 chunks (row=c>>3, kc=c&7), 8/thread
#pragma unroll
            for (int j = 0; j < 8; ++j) {
                const int c = pt * 8 + j, row = c >> 3, kc = c & 7;
                cp_async16(st + sw_off(row, kc),
                           A + (long long)(bm + row) * lda + k0 + kc * 8);
            }
            // B: 2048 chunks, 16/thread
#pragma unroll
            for (int j = 0; j < 16; ++j) {
                const int c = pt * 16 + j, row = c >> 3, kc = c & 7;
                cp_async16(st + A_BYTES + sw_off(row, kc),
                           B + (long long)(bn + row) * ldb + k0 + kc * 8);
            }
            cp_async_arrive(mb + 8 * s);
        }
        return;
    }

    // --------------------------- compute warps ------------------------------
    const int wm = wid & 3;      // 4 warps over M (32 rows each)
    const int wn = wid >> 2;     // 4 warps over N (64 cols each)
    const int g = lane >> 2;
    const int t = lane & 3;

    float acc[2][8][4];
#pragma unroll
    for (int i = 0; i < 2; ++i)
#pragma unroll
        for (int j = 0; j < 8; ++j)
#pragma unroll
            for (int q = 0; q < 4; ++q) acc[i][j][q] = 0.f;

    for (int i = 0; i < nk; ++i) {
        const int s = i & (NST - 1);
        const int u = i >> 2;
        MB_WAIT_PARITY(mb + 8 * s, (uint32_t)(u & 1));
        const uint32_t stA = sb0 + (uint32_t)s * STAGE_BYTES;
        const uint32_t stB = stA + A_BYTES;
#pragma unroll
        for (int ks = 0; ks < 4; ++ks) {
            uint32_t av[2][4], bv[4][4];
#pragma unroll
            for (int mt = 0; mt < 2; ++mt)
                ldsm4(av[mt], ldsm_addr(stA, wm * 32 + mt * 16, ks, lane));
#pragma unroll
            for (int nt = 0; nt < 4; ++nt)
                ldsm4(bv[nt], ldsm_addr(stB, wn * 64 + nt * 16, ks, lane));
            // all smem reads for this stage are in flight — release early.
            if (ks == 3) MB_ARRIVE(mb + 32 + 8 * s);
#pragma unroll
            for (int mt = 0; mt < 2; ++mt)
#pragma unroll
                for (int nt = 0; nt < 4; ++nt) {
                    mma16(acc[mt][2 * nt],     av[mt], bv[nt][0], bv[nt][2]);
                    mma16(acc[mt][2 * nt + 1], av[mt], bv[nt][1], bv[nt][3]);
                }
        }
    }

    // epilogue
    if (out_half) {
        __half* C = (__half*)Cv + (long long)blockIdx.z * sC;
#pragma unroll
        for (int im = 0; im < 2; ++im) {
            const int r0 = bm + wm * 32 + im * 16 + g;
#pragma unroll
            for (int nj = 0; nj < 8; ++nj) {
                const int c0 = bn + wn * 64 + nj * 8 + 2 * t;
                const float b0 = bias ? __ldg(bias + c0) : 0.f;
                const float b1 = bias ? __ldg(bias + c0 + 1) : 0.f;
                *(__half2*)&C[(long long)r0 * ldc + c0] =
                    __floats2half2_rn(acc[im][nj][0] * alpha + b0,
                                      acc[im][nj][1] * alpha + b1);
                *(__half2*)&C[(long long)(r0 + 8) * ldc + c0] =
                    __floats2half2_rn(acc[im][nj][2] * alpha + b0,
                                      acc[im][nj][3] * alpha + b1);
            }
        }
    } else {
        float* C = (float*)Cv + (long long)blockIdx.z * sC;
#pragma unroll
        for (int im = 0; im < 2; ++im) {
            const int r0 = bm + wm * 32 + im * 16 + g;
#pragma unroll
            for (int nj = 0; nj < 8; ++nj) {
                const int c0 = bn + wn * 64 + nj * 8 + 2 * t;
                float2 v0 = { acc[im][nj][0] * alpha, acc[im][nj][1] * alpha };
                float2 v1 = { acc[im][nj][2] * alpha, acc[im][nj][3] * alpha };
                *(float2*)&C[(long long)r0 * ldc + c0]       = v0;
                *(float2*)&C[(long long)(r0 + 8) * ldc + c0] = v1;
            }
        }
    }
}

// ----------------------------- aux kernels ---------------------------------

__global__ void __launch_bounds__(256)
f2h_k(const float2* __restrict__ in, __half2* __restrict__ out, int n2)
{
    const int i = blockIdx.x * 256 + threadIdx.x;
    if (i < n2) {
        float2 v = in[i];
        out[i] = __floats2half2_rn(v.x, v.y);
    }
}

__global__ void __launch_bounds__(256)
pack_bias_k(const float* __restrict__ bq, const float* __restrict__ bk,
            const float* __restrict__ bv, float* __restrict__ b3)
{
    const int i = blockIdx.x * 256 + threadIdx.x;
    if (i < N3)
        b3[i] = (i < DIM) ? bq[i] : (i < 2 * DIM) ? bk[i - DIM] : bv[i - 2 * DIM];
}

// all three W^T -> fp16 in one launch (grid.z selects source)
__global__ void __launch_bounds__(256)
tr_f2h3(const float* __restrict__ Wq, const float* __restrict__ Wk,
        const float* __restrict__ Wv, __half* __restrict__ out)
{
    __shared__ float tsm[32][33];
    const float* in = (blockIdx.z == 0) ? Wq : (blockIdx.z == 1) ? Wk : Wv;
    out += (size_t)blockIdx.z * DIM * DIM;
    const int bx = blockIdx.x * 32, by = blockIdx.y * 32;
    const int tx = threadIdx.x & 31, ty = threadIdx.x >> 5;
#pragma unroll
    for (int d = 0; d < 4; ++d)
        tsm[ty + d * 8][tx] = in[(long long)(by + ty + d * 8) * DIM + bx + tx];
    __syncthreads();
#pragma unroll
    for (int d = 0; d < 4; ++d)
        out[(long long)(bx + ty + d * 8) * DIM + by + tx] =
            __float2half_rn(tsm[tx][ty + d * 8]);
}

// Merged: blocks [0, BATCH*SEQ) do row softmax (S fp32 -> A fp16);
// blocks [BATCH*SEQ, 2*BATCH*SEQ) transpose V (QKV layout) -> Vt.
// Both are independent; one launch overlaps their latency.
#define NSMAX (BATCH * SEQ)
__global__ void __launch_bounds__(256)
softmax_trv(const float* __restrict__ S, __half* __restrict__ A,
            const __half* __restrict__ V, __half* __restrict__ Vt)
{
    __shared__ __align__(16) float shm[32 * 33];
    const int tid = threadIdx.x;

    if (blockIdx.x < NSMAX) {
        // ---------------- softmax over one 2048-wide row --------------------
        const long long base = (long long)blockIdx.x * SEQ;
        const int lane = tid & 31, wid = tid >> 5;
        const float4* S4 = (const float4*)(S + base);
        float4 w[2];
        float m = -1e30f;
#pragma unroll
        for (int j = 0; j < 2; ++j) {
            w[j] = S4[tid + j * 256];
            m = fmaxf(m, fmaxf(fmaxf(w[j].x, w[j].y), fmaxf(w[j].z, w[j].w)));
        }
        float* red = shm;
#pragma unroll
        for (int o = 16; o > 0; o >>= 1) m = fmaxf(m, __shfl_xor_sync(0xffffffffu, m, o));
        if (lane == 0) red[wid] = m;
        __syncthreads();
        float mr = red[0];
#pragma unroll
        for (int i = 1; i < 8; ++i) mr = fmaxf(mr, red[i]);
        __syncthreads();
        float sum = 0.f;
#pragma unroll
        for (int j = 0; j < 2; ++j) {
            w[j].x = expf(w[j].x - mr); w[j].y = expf(w[j].y - mr);
            w[j].z = expf(w[j].z - mr); w[j].w = expf(w[j].w - mr);
            sum += (w[j].x + w[j].y) + (w[j].z + w[j].w);
        }
#pragma unroll
        for (int o = 16; o > 0; o >>= 1) sum += __shfl_xor_sync(0xffffffffu, sum, o);
        if (lane == 0) red[wid] = sum;
        __syncthreads();
        float st = 0.f;
#pragma unroll
        for (int i = 0; i < 8; ++i) st += red[i];
        const float inv = 1.0f / st;
        __half2* A2 = (__half2*)(A + base);
#pragma unroll
        for (int j = 0; j < 2; ++j) {
            A2[(tid + j * 256) * 2]     = __floats2half2_rn(w[j].x * inv, w[j].y * inv);
            A2[(tid + j * 256) * 2 + 1] = __floats2half2_rn(w[j].z * inv, w[j].w * inv);
        }
    } else {
        // ---------------- V transpose: Vt[b][d][t] = V[b][t][d] -------------
        __half* tsm = (__half*)shm;   // 32*33 halves fit easily
        const int bid = blockIdx.x - NSMAX;
        const int z   = bid >> 11;          // batch (2048 blocks per batch)
        const int rem = bid & 2047;
        const int bx  = (rem & 31) * 32;    // over DIM
        const int by  = (rem >> 5) * 32;    // over SEQ
        const __half* Vb = V + (long long)z * SEQ * N3;
        __half* Vtb = Vt + (long long)z * DIM * SEQ;
        const int tx = tid & 31, ty = tid >> 5;
#pragma unroll
        for (int d = 0; d < 4; ++d)
            tsm[(ty + d * 8) * 33 + tx] =
                Vb[(long long)(by + ty + d * 8) * N3 + bx + tx];
        __syncthreads();
#pragma unroll
        for (int d = 0; d < 4; ++d)
            Vtb[(long long)(bx + ty + d * 8) * SEQ + by + tx] =
                tsm[tx * 33 + ty + d * 8];
    }
}

// ------------------------------- launcher ----------------------------------

extern "C" void kernel_launch(void* const* d_in, const int* in_sizes, int n_in,
                              void* d_out, int out_size)
{
    (void)in_sizes; (void)n_in; (void)out_size;
    const float* x  = (const float*)d_in[0];
    const float* Wq = (const float*)d_in[1];
    const float* bq = (const float*)d_in[2];
    const float* Wk = (const float*)d_in[3];
    const float* bk = (const float*)d_in[4];
    const float* Wv = (const float*)d_in[5];
    const float* bv = (const float*)d_in[6];
    float* out = (float*)d_out;

    __half *xh, *Wt, *QKV, *Ap, *Vt;
    float *Sp, *b3;
    cudaGetSymbolAddress((void**)&xh,  g_xh);
    cudaGetSymbolAddress((void**)&Wt,  g_Wt);
    cudaGetSymbolAddress((void**)&QKV, g_QKV);
    cudaGetSymbolAddress((void**)&Sp,  g_S);
    cudaGetSymbolAddress((void**)&Ap,  g_A);
    cudaGetSymbolAddress((void**)&Vt,  g_Vt);
    cudaGetSymbolAddress((void**)&b3,  g_b3);

    cudaFuncSetAttribute(gemm_nt_h, cudaFuncAttributeMaxDynamicSharedMemorySize, SMEM_DYN);

    f2h_k<<<MTOT * DIM / 512, 256>>>((const float2*)x, (__half2*)xh, MTOT * DIM / 2);
    pack_bias_k<<<(N3 + 255) / 256, 256>>>(bq, bk, bv, b3);

    dim3 tb(256), tgw(DIM / 32, DIM / 32, 3);
    tr_f2h3<<<tgw, tb>>>(Wq, Wk, Wv, Wt);

    dim3 blk(NTHREADS);

    // fused QKV: [16384,1024] @ [3072,1024]^T -> half + bias
    dim3 gq(N3 / BN, MTOT / BM, 1);
    gemm_nt_h<<<gq, blk, SMEM_DYN>>>(xh, Wt, b3, QKV,
                                     DIM, DIM, N3, 1.f, 1, DIM / BK, 0, 0, 0);

    // scores = Q @ K^T / 32 per batch -> fp32
    dim3 gs(SEQ / BN, SEQ / BM, BATCH);
    gemm_nt_h<<<gs, blk, SMEM_DYN>>>(QKV, QKV + DIM, nullptr, Sp,
                                     N3, N3, SEQ, 0.03125f, 0, DIM / BK,
                                     (long long)SEQ * N3, (long long)SEQ * N3,
                                     (long long)SEQ * SEQ);

    // merged softmax (S->A) + V transpose (QKV->Vt) — independent work
    softmax_trv<<<2 * NSMAX, 256>>>(Sp, Ap, QKV + 2 * DIM, Vt);

    // out = A @ V per batch -> fp32
    dim3 go(DIM / BN, SEQ / BM, BATCH);
    gemm_nt_h<<<go, blk, SMEM_DYN>>>(Ap, Vt, nullptr, out,
                                     SEQ, SEQ, DIM, 1.f, 0, SEQ / BK,
                                     (long long)SEQ * SEQ, (long long)DIM * SEQ,
                                     (long long)SEQ * DIM);
}

// round 17
// speedup vs baseline: 1.2887x; 1.2887x over previous
#include <cuda_runtime.h>
#include <cuda_fp16.h>
#include <cstdint>

// ---------------------------------------------------------------------------
// Fused single-head attention, fp32 in/out. fp16 mma.sync (m16n8k16) GEMMs.
// CTA tile 128x256, BK=64, NST=4 (192KB smem), 16 compute + 2 producer warps.
// Early empty-arrive; merged softmax + V-transpose aux kernel.
//   B=8, S=2048, D=1024
// ---------------------------------------------------------------------------

#define BATCH 8
#define SEQ   2048
#define DIM   1024
#define MTOT  (BATCH * SEQ)      // 16384
#define N3    (3 * DIM)          // 3072

#define BM 128
#define BN 256
#define BK 64
#define NST 4
#define A_BYTES 16384            // 128 rows * 128 B
#define STAGE_BYTES 49152        // A 16384 + B 32768
#define SMEM_DYN (NST * STAGE_BYTES)
#define NTHREADS 576             // 16 compute warps + 2 producer warps

// scratch (device globals — no cudaMalloc allowed)
__device__ __half g_xh[(size_t)MTOT * DIM];
__device__ __half g_Wt[3 * (size_t)DIM * DIM];
__device__ __half g_QKV[(size_t)MTOT * N3];
__device__ float  g_S[(size_t)BATCH * SEQ * SEQ];
__device__ __half g_A[(size_t)BATCH * SEQ * SEQ];
__device__ __half g_Vt[(size_t)BATCH * DIM * SEQ];
__device__ float  g_b3[N3];

__device__ __forceinline__ uint32_t smem_u32(const void* p) {
    uint32_t a;
    asm("{ .reg .u64 t; cvta.to.shared.u64 t, %1; cvt.u32.u64 %0, t; }" : "=r"(a) : "l"(p));
    return a;
}

__device__ __forceinline__ void cp_async16(uint32_t dst, const void* src) {
    asm volatile("cp.async.cg.shared.global [%0], [%1], 16;" :: "r"(dst), "l"(src) : "memory");
}
__device__ __forceinline__ void cp_async_arrive(uint32_t mbar) {
    asm volatile("cp.async.mbarrier.arrive.noinc.shared::cta.b64 [%0];" :: "r"(mbar) : "memory");
}

#define MB_INIT(addr, cnt) \
    asm volatile("mbarrier.init.shared.b64 [%0], %1;" :: "r"(addr), "r"((uint32_t)(cnt)) : "memory")
#define MB_ARRIVE(addr) \
    asm volatile("mbarrier.arrive.release.cta.shared::cta.b64 _, [%0];" :: "r"(addr) : "memory")
#define MB_WAIT_PARITY(addr, parity) do {                                              \
    uint32_t _m = (addr); uint32_t _p = (parity); uint32_t _d;                         \
    asm volatile("{ .reg .pred p; mbarrier.try_wait.parity.acquire.cta.shared::cta.b64 p, [%1], %2; selp.b32 %0, 1, 0, p; }" \
                 : "=r"(_d) : "r"(_m), "r"(_p) : "memory");                            \
    while (!_d) {                                                                      \
        asm volatile("{ .reg .pred p; mbarrier.try_wait.parity.acquire.cta.shared::cta.b64 p, [%1], %2, 0x989680; selp.b32 %0, 1, 0, p; }" \
                     : "=r"(_d) : "r"(_m), "r"(_p) : "memory");                        \
    }                                                                                  \
} while (0)

__device__ __forceinline__ void ldsm4(uint32_t* r, uint32_t addr) {
    asm volatile("ldmatrix.sync.aligned.m8n8.x4.shared.b16 {%0,%1,%2,%3}, [%4];"
        : "=r"(r[0]), "=r"(r[1]), "=r"(r[2]), "=r"(r[3]) : "r"(addr));
}

__device__ __forceinline__ void mma16(float* c, const uint32_t* a, uint32_t b0, uint32_t b1) {
    asm volatile(
        "mma.sync.aligned.m16n8k16.row.col.f32.f16.f16.f32 "
        "{%0,%1,%2,%3}, {%4,%5,%6,%7}, {%8,%9}, {%0,%1,%2,%3};"
        : "+f"(c[0]), "+f"(c[1]), "+f"(c[2]), "+f"(c[3])
        : "r"(a[0]), "r"(a[1]), "r"(a[2]), "r"(a[3]), "r"(b0), "r"(b1));
}

// smem tile rows of 128B (64 halves); 16B-chunk swizzle c ^= (row & 7)
__device__ __forceinline__ uint32_t sw_off(int row, int kc) {
    return (uint32_t)(row * 128 + ((kc ^ (row & 7)) << 4));
}
__device__ __forceinline__ uint32_t ldsm_addr(uint32_t base, int rowbase, int ks, int lane) {
    const int row = rowbase + (lane & 7) + (lane & 8);
    const int kc = 2 * ks + ((lane >> 4) & 1);
    return base + sw_off(row, kc);
}

// ------------------------------ GEMM ---------------------------------------
// C[M,N] = alpha * A[M,K] @ B[N,K]^T (+bias). A,B fp16 K-major.
// out_half: 1 -> C half, 0 -> C float. K = nk*64. M%128==0, N%256==0.
__global__ void __launch_bounds__(NTHREADS, 1)
gemm_nt_h(const __half* __restrict__ A, const __half* __restrict__ B,
          const float* __restrict__ bias, void* __restrict__ Cv,
          int lda, int ldb, int ldc, float alpha, int out_half, int nk,
          long long sA, long long sB, long long sC)
{
    extern __shared__ char smem[];
    __shared__ __align__(8) unsigned long long mbar[2 * NST];

    A += (long long)blockIdx.z * sA;
    B += (long long)blockIdx.z * sB;

    const int bm = blockIdx.y * BM;
    const int bn = blockIdx.x * BN;
    const int tid  = threadIdx.x;
    const int lane = tid & 31;
    const int wid  = tid >> 5;

    const uint32_t sb0 = smem_u32(smem);
    const uint32_t mb  = smem_u32(&mbar[0]);   // full[s]=mb+8s, empty[s]=mb+32+8s

    if (tid == 0) {
#pragma unroll
        for (int s = 0; s < NST; ++s) {
            MB_INIT(mb + 8 * s, 64);        // full: 64 producer threads
            MB_INIT(mb + 32 + 8 * s, 512);  // empty: 512 compute threads
        }
    }
    __syncthreads();

    if (wid >= 16) {
        // ------------------------- producer warps (2) ----------------------
        const int pt = tid - 512;   // 0..63
        for (int i = 0; i < nk; ++i) {
            const int s = i & (NST - 1);
            const int u = i >> 2;
            if (i >= NST) MB_WAIT_PARITY(mb + 32 + 8 * s, (uint32_t)((u - 1) & 1));
            const uint32_t st = sb0 + (uint32_t)s * STAGE_BYTES;
            const int k0 = i * BK;
            // A: 1024 chunks (row=c>>3, kc=c&7), 16/thread
#pragma unroll
            for (int j = 0; j < 16; ++j) {
                const int c = pt * 16 + j, row = c >> 3, kc = c & 7;
                cp_async16(st + sw_off(row, kc),
                           A + (long long)(bm + row) * lda + k0 + kc * 8);
            }
            // B: 2048 chunks, 32/thread
#pragma unroll
            for (int j = 0; j < 32; ++j) {
                const int c = pt * 32 + j, row = c >> 3, kc = c & 7;
                cp_async16(st + A_BYTES + sw_off(row, kc),
                           B + (long long)(bn + row) * ldb + k0 + kc * 8);
            }
            cp_async_arrive(mb + 8 * s);
        }
        return;
    }

    // --------------------------- compute warps ------------------------------
    const int wm = wid & 3;      // 4 warps over M (32 rows each)
    const int wn = wid >> 2;     // 4 warps over N (64 cols each)
    const int g = lane >> 2;
    const int t = lane & 3;

    float acc[2][8][4];
#pragma unroll
    for (int i = 0; i < 2; ++i)
#pragma unroll
        for (int j = 0; j < 8; ++j)
#pragma unroll
            for (int q = 0; q < 4; ++q) acc[i][j][q] = 0.f;

    for (int i = 0; i < nk; ++i) {
        const int s = i & (NST - 1);
        const int u = i >> 2;
        MB_WAIT_PARITY(mb + 8 * s, (uint32_t)(u & 1));
        const uint32_t stA = sb0 + (uint32_t)s * STAGE_BYTES;
        const uint32_t stB = stA + A_BYTES;
#pragma unroll
        for (int ks = 0; ks < 4; ++ks) {
            uint32_t av[2][4], bv[4][4];
#pragma unroll
            for (int mt = 0; mt < 2; ++mt)
                ldsm4(av[mt], ldsm_addr(stA, wm * 32 + mt * 16, ks, lane));
#pragma unroll
            for (int nt = 0; nt < 4; ++nt)
                ldsm4(bv[nt], ldsm_addr(stB, wn * 64 + nt * 16, ks, lane));
            // all smem reads for this stage are in flight — release early.
            if (ks == 3) MB_ARRIVE(mb + 32 + 8 * s);
#pragma unroll
            for (int mt = 0; mt < 2; ++mt)
#pragma unroll
                for (int nt = 0; nt < 4; ++nt) {
                    mma16(acc[mt][2 * nt],     av[mt], bv[nt][0], bv[nt][2]);
                    mma16(acc[mt][2 * nt + 1], av[mt], bv[nt][1], bv[nt][3]);
                }
        }
    }

    // epilogue
    if (out_half) {
        __half* C = (__half*)Cv + (long long)blockIdx.z * sC;
#pragma unroll
        for (int im = 0; im < 2; ++im) {
            const int r0 = bm + wm * 32 + im * 16 + g;
#pragma unroll
            for (int nj = 0; nj < 8; ++nj) {
                const int c0 = bn + wn * 64 + nj * 8 + 2 * t;
                const float b0 = bias ? __ldg(bias + c0) : 0.f;
                const float b1 = bias ? __ldg(bias + c0 + 1) : 0.f;
                *(__half2*)&C[(long long)r0 * ldc + c0] =
                    __floats2half2_rn(acc[im][nj][0] * alpha + b0,
                                      acc[im][nj][1] * alpha + b1);
                *(__half2*)&C[(long long)(r0 + 8) * ldc + c0] =
                    __floats2half2_rn(acc[im][nj][2] * alpha + b0,
                                      acc[im][nj][3] * alpha + b1);
            }
        }
    } else {
        float* C = (float*)Cv + (long long)blockIdx.z * sC;
#pragma unroll
        for (int im = 0; im < 2; ++im) {
            const int r0 = bm + wm * 32 + im * 16 + g;
#pragma unroll
            for (int nj = 0; nj < 8; ++nj) {
                const int c0 = bn + wn * 64 + nj * 8 + 2 * t;
                float2 v0 = { acc[im][nj][0] * alpha, acc[im][nj][1] * alpha };
                float2 v1 = { acc[im][nj][2] * alpha, acc[im][nj][3] * alpha };
                *(float2*)&C[(long long)r0 * ldc + c0]       = v0;
                *(float2*)&C[(long long)(r0 + 8) * ldc + c0] = v1;
            }
        }
    }
}

// ----------------------------- aux kernels ---------------------------------

__global__ void __launch_bounds__(256)
f2h_k(const float2* __restrict__ in, __half2* __restrict__ out, int n2)
{
    const int i = blockIdx.x * 256 + threadIdx.x;
    if (i < n2) {
        float2 v = in[i];
        out[i] = __floats2half2_rn(v.x, v.y);
    }
}

__global__ void __launch_bounds__(256)
pack_bias_k(const float* __restrict__ bq, const float* __restrict__ bk,
            const float* __restrict__ bv, float* __restrict__ b3)
{
    const int i = blockIdx.x * 256 + threadIdx.x;
    if (i < N3)
        b3[i] = (i < DIM) ? bq[i] : (i < 2 * DIM) ? bk[i - DIM] : bv[i - 2 * DIM];
}

// all three W^T -> fp16 in one launch (grid.z selects source)
__global__ void __launch_bounds__(256)
tr_f2h3(const float* __restrict__ Wq, const float* __restrict__ Wk,
        const float* __restrict__ Wv, __half* __restrict__ out)
{
    __shared__ float tsm[32][33];
    const float* in = (blockIdx.z == 0) ? Wq : (blockIdx.z == 1) ? Wk : Wv;
    out += (size_t)blockIdx.z * DIM * DIM;
    const int bx = blockIdx.x * 32, by = blockIdx.y * 32;
    const int tx = threadIdx.x & 31, ty = threadIdx.x >> 5;
#pragma unroll
    for (int d = 0; d < 4; ++d)
        tsm[ty + d * 8][tx] = in[(long long)(by + ty + d * 8) * DIM + bx + tx];
    __syncthreads();
#pragma unroll
    for (int d = 0; d < 4; ++d)
        out[(long long)(bx + ty + d * 8) * DIM + by + tx] =
            __float2half_rn(tsm[tx][ty + d * 8]);
}

// Merged: blocks [0, BATCH*SEQ) do row softmax (S fp32 -> A fp16);
// blocks [BATCH*SEQ, 2*BATCH*SEQ) transpose V (QKV layout) -> Vt.
// Independent work items; one launch overlaps their latency.
#define NSMAX (BATCH * SEQ)
__global__ void __launch_bounds__(256)
softmax_trv(const float* __restrict__ S, __half* __restrict__ A,
            const __half* __restrict__ V, __half* __restrict__ Vt)
{
    __shared__ __align__(16) float shm[32 * 33];
    const int tid = threadIdx.x;

    if (blockIdx.x < NSMAX) {
        // ---------------- softmax over one 2048-wide row --------------------
        const long long base = (long long)blockIdx.x * SEQ;
        const int lane = tid & 31, wid = tid >> 5;
        const float4* S4 = (const float4*)(S + base);
        float4 w[2];
        float m = -1e30f;
#pragma unroll
        for (int j = 0; j < 2; ++j) {
            w[j] = S4[tid + j * 256];
            m = fmaxf(m, fmaxf(fmaxf(w[j].x, w[j].y), fmaxf(w[j].z, w[j].w)));
        }
        float* red = shm;
#pragma unroll
        for (int o = 16; o > 0; o >>= 1) m = fmaxf(m, __shfl_xor_sync(0xffffffffu, m, o));
        if (lane == 0) red[wid] = m;
        __syncthreads();
        float mr = red[0];
#pragma unroll
        for (int i = 1; i < 8; ++i) mr = fmaxf(mr, red[i]);
        __syncthreads();
        float sum = 0.f;
#pragma unroll
        for (int j = 0; j < 2; ++j) {
            w[j].x = expf(w[j].x - mr); w[j].y = expf(w[j].y - mr);
            w[j].z = expf(w[j].z - mr); w[j].w = expf(w[j].w - mr);
            sum += (w[j].x + w[j].y) + (w[j].z + w[j].w);
        }
#pragma unroll
        for (int o = 16; o > 0; o >>= 1) sum += __shfl_xor_sync(0xffffffffu, sum, o);
        if (lane == 0) red[wid] = sum;
        __syncthreads();
        float st = 0.f;
#pragma unroll
        for (int i = 0; i < 8; ++i) st += red[i];
        const float inv = 1.0f / st;
        __half2* A2 = (__half2*)(A + base);
#pragma unroll
        for (int j = 0; j < 2; ++j) {
            A2[(tid + j * 256) * 2]     = __floats2half2_rn(w[j].x * inv, w[j].y * inv);
            A2[(tid + j * 256) * 2 + 1] = __floats2half2_rn(w[j].z * inv, w[j].w * inv);
        }
    } else {
        // ---------------- V transpose: Vt[b][d][t] = V[b][t][d] -------------
        __half* tsm = (__half*)shm;   // 32*33 halves fit easily
        const int bid = blockIdx.x - NSMAX;
        const int z   = bid >> 11;          // batch (2048 blocks per batch)
        const int rem = bid & 2047;
        const int bx  = (rem & 31) * 32;    // over DIM
        const int by  = (rem >> 5) * 32;    // over SEQ
        const __half* Vb = V + (long long)z * SEQ * N3;
        __half* Vtb = Vt + (long long)z * DIM * SEQ;
        const int tx = tid & 31, ty = tid >> 5;
#pragma unroll
        for (int d = 0; d < 4; ++d)
            tsm[(ty + d * 8) * 33 + tx] =
                Vb[(long long)(by + ty + d * 8) * N3 + bx + tx];
        __syncthreads();
#pragma unroll
        for (int d = 0; d < 4; ++d)
            Vtb[(long long)(bx + ty + d * 8) * SEQ + by + tx] =
                tsm[tx * 33 + ty + d * 8];
    }
}

// ------------------------------- launcher ----------------------------------

extern "C" void kernel_launch(void* const* d_in, const int* in_sizes, int n_in,
                              void* d_out, int out_size)
{
    (void)in_sizes; (void)n_in; (void)out_size;
    const float* x  = (const float*)d_in[0];
    const float* Wq = (const float*)d_in[1];
    const float* bq = (const float*)d_in[2];
    const float* Wk = (const float*)d_in[3];
    const float* bk = (const float*)d_in[4];
    const float* Wv = (const float*)d_in[5];
    const float* bv = (const float*)d_in[6];
    float* out = (float*)d_out;

    __half *xh, *Wt, *QKV, *Ap, *Vt;
    float *Sp, *b3;
    cudaGetSymbolAddress((void**)&xh,  g_xh);
    cudaGetSymbolAddress((void**)&Wt,  g_Wt);
    cudaGetSymbolAddress((void**)&QKV, g_QKV);
    cudaGetSymbolAddress((void**)&Sp,  g_S);
    cudaGetSymbolAddress((void**)&Ap,  g_A);
    cudaGetSymbolAddress((void**)&Vt,  g_Vt);
    cudaGetSymbolAddress((void**)&b3,  g_b3);

    cudaFuncSetAttribute(gemm_nt_h, cudaFuncAttributeMaxDynamicSharedMemorySize, SMEM_DYN);

    f2h_k<<<MTOT * DIM / 512, 256>>>((const float2*)x, (__half2*)xh, MTOT * DIM / 2);
    pack_bias_k<<<(N3 + 255) / 256, 256>>>(bq, bk, bv, b3);

    dim3 tb(256), tgw(DIM / 32, DIM / 32, 3);
    tr_f2h3<<<tgw, tb>>>(Wq, Wk, Wv, Wt);

    dim3 blk(NTHREADS);

    // fused QKV: [16384,1024] @ [3072,1024]^T -> half + bias
    dim3 gq(N3 / BN, MTOT / BM, 1);
    gemm_nt_h<<<gq, blk, SMEM_DYN>>>(xh, Wt, b3, QKV,
                                     DIM, DIM, N3, 1.f, 1, DIM / BK, 0, 0, 0);

    // scores = Q @ K^T / 32 per batch -> fp32
    dim3 gs(SEQ / BN, SEQ / BM, BATCH);
    gemm_nt_h<<<gs, blk, SMEM_DYN>>>(QKV, QKV + DIM, nullptr, Sp,
                                     N3, N3, SEQ, 0.03125f, 0, DIM / BK,
                                     (long long)SEQ * N3, (long long)SEQ * N3,
                                     (long long)SEQ * SEQ);

    // merged softmax (S->A) + V transpose (QKV->Vt) — independent work
    softmax_trv<<<2 * NSMAX, 256>>>(Sp, Ap, QKV + 2 * DIM, Vt);

    // out = A @ V per batch -> fp32
    dim3 go(DIM / BN, SEQ / BM, BATCH);
    gemm_nt_h<<<go, blk, SMEM_DYN>>>(Ap, Vt, nullptr, out,
                                     SEQ, SEQ, DIM, 1.f, 0, SEQ / BK,
                                     (long long)SEQ * SEQ, (long long)DIM * SEQ,
                                     (long long)SEQ * DIM);
}